// round 13
// baseline (speedup 1.0000x reference)
#include <cuda_runtime.h>
#include <math.h>

#define BB 16
#define NN 8400
#define GG 128
#define NCL 5
#define BN (BB*NN)      // 134400
#define BGT (BB*GG)     // 2048
#define NQ4 (NN/4)      // 2100 float4s per row
#define MAXTK 18
#define EPSF 1e-9f
#define HPI_F 1.57079632679489662f
#define PI_F  3.14159265358979323f
#define IPI_F 0.318309886183790672f
#define BSPLIT 11       // default stream handles b in [0,11), side stream [11,16)

typedef unsigned long long u64;

struct GTC {
    float gx, gy, ct, st;
    float w15, h15, inv_s2, inv_sc2;
    float factor, gth;
    int budget, fbk, flags, lbl;
    float pad0, pad1;
};

__device__ GTC           d_gt[BGT];
__device__ float         d_am[(size_t)BGT * NN];  // [b][g][n]
__device__ u64           d_best[BN];              // (val<<32)|(127-g)
__device__ int           d_norm[BN];
__device__ unsigned char d_pos[BN];
__device__ int           d_cnt[BGT];              // nonzero in-center flag

// ---------------------------------------------------------------------------
__global__ __launch_bounds__(256) void prep_gt(const int* __restrict__ gl,
                                               const float* __restrict__ gb,
                                               const float* __restrict__ mg) {
    int bg = blockIdx.x * 256 + threadIdx.x;
    if (bg >= BGT) return;
    const float* g = gb + (size_t)bg * 5;
    float gx = g[0], gy = g[1], w = g[2], h = g[3], th = g[4];
    float wc = fmaxf(w, EPSF), hc = fmaxf(h, EPSF);
    float area = wc * hc;
    float ar = fmaxf(wc / hc, hc / wc);
    float sev = fminf(fmaxf((0.01f - area) / (0.01f + EPSF), 0.f), 1.f);
    int te = (int)ceilf(sev * 4.f);
    int el = (ar >= 4.f) ? 1 : 0;
    GTC q;
    q.gx = gx; q.gy = gy;
    q.ct = cosf(-th); q.st = sinf(-th);
    q.w15 = w * 1.5f; q.h15 = h * 1.5f;
    float sc = sqrtf(w * h);
    float is = 1.f / (sc + 1e-6f);         q.inv_s2  = is * is;
    float isc = 1.f / (sc * 1.5f + 1e-6f); q.inv_sc2 = isc * isc;
    float strength = fminf(fmaxf((ar - 4.f) / (4.f + EPSF), 0.f), 1.f);
    q.factor = (1.f + sev * (4.f / 13.f)) * (1.f + 0.25f * strength);
    q.gth = th;
    q.budget = 13 + te + el;
    q.fbk = te + el + 3;
    int fl = (mg[bg] > 0.f) ? 1 : 0;
    if ((area < 0.01f) || (ar >= 4.f)) fl |= 2;
    q.flags = fl;
    q.lbl = gl[bg];
    if (!(fl & 1)) q.factor = 0.f;   // masked GT: body yields exactly 0
    q.pad0 = 0.f; q.pad1 = 0.f;
    d_gt[bg] = q;
    d_cnt[bg] = 0;
}

// ---------------------------------------------------------------------------
// A (R11, pinned): block = (512-anchor tile, b0+by), 512 threads, 1 anchor/thr.
// ---------------------------------------------------------------------------
__global__ __launch_bounds__(512) void pair_kernel(const float2* __restrict__ anch,
                                                   const float* __restrict__ ps,
                                                   const float* __restrict__ pbx,
                                                   int b0) {
    int b   = b0 + blockIdx.y;
    int tid = threadIdx.x;
    int n   = blockIdx.x * 512 + tid;

    __shared__ GTC           s_gt[GG];     // 8 KB
    __shared__ unsigned char s_any[GG];

    {
        const float4* src = (const float4*)(d_gt + b * GG);
        float4*       dst = (float4*)s_gt;
        dst[tid] = src[tid];
        if (tid < GG) s_any[tid] = 0;
    }
    __syncthreads();

    bool valid = (n < NN);
    float ax = 0.f, ay = 0.f, px = 0.f, py = 0.f, pt = 0.f;
    float l0 = 0.f, l1 = 0.f, l2 = 0.f, l3 = 0.f, l4 = 0.f;
    if (valid) {
        float2 a = anch[n];
        ax = a.x; ay = a.y;
        size_t base = (size_t)(b * NN + n) * 5;
        px = pbx[base]; py = pbx[base + 1]; pt = pbx[base + 4];
#define LC(d, i) { float sg = 1.f/(1.f+__expf(-ps[base+(i)])); \
                   sg = fminf(fmaxf(sg, EPSF), 1.f); d = 0.5f*__logf(sg+EPSF); }
        LC(l0,0) LC(l1,1) LC(l2,2) LC(l3,3) LC(l4,4)
#undef LC
    }

    float bv = 0.f;
    int   bgi = 0;
    float* amp = d_am + (size_t)b * GG * NN + n;

#pragma unroll 2
    for (int g = 0; g < GG; g++) {
        GTC q = s_gt[g];
        float dxa = ax - q.gx, dya = ay - q.gy;
        float lx = dxa * q.ct - dya * q.st;
        float ly = dxa * q.st + dya * q.ct;
        bool in = valid && (fabsf(lx) < q.w15) && (fabsf(ly) < q.h15);

        float dxp = px - q.gx, dyp = py - q.gy;
        float t = (dxp * dxp + dyp * dyp) * q.inv_s2;
        float x = __expf(-t) + EPSF;
        float x2 = x * x; float x6 = x2 * x2 * x2;
        float wv = (pt - q.gth) + HPI_F;
        wv -= PI_F * floorf(wv * IPI_F);
        float wr = fabsf(wv - HPI_F);
        float c = (dxa * dxa + dya * dya) * q.inv_sc2;
        int lb = q.lbl;
        float lcl = lb == 0 ? l0 : (lb == 1 ? l1 : (lb == 2 ? l2 : (lb == 3 ? l3 : l4)));
        float val = fmaxf(q.factor * x6 * __expf(lcl - 1.5f * wr - c), 0.f);
        float vv = in ? val : 0.f;

        if (in) s_any[g] = 1;
        if (valid) amp[(size_t)g * NN] = vv;
        if (vv > bv) { bv = vv; bgi = g; }
    }
    __syncthreads();
    if (tid < GG && s_any[tid]) atomicOr(&d_cnt[b * GG + tid], 1);
    if (valid) {
        int idx = b * NN + n;
        d_best[idx] = ((u64)__float_as_uint(bv) << 32) | (unsigned)(127 - bgi);
        d_norm[idx] = 0;
        d_pos[idx]  = 0;
    }
}

// ---------------------------------------------------------------------------
// B (pinned): block per (b,g), bg = blockIdx.x + b0*GG.
// ---------------------------------------------------------------------------
__global__ __launch_bounds__(256) void topk_kernel(const float2* __restrict__ anch,
                                                   const float* __restrict__ ps,
                                                   const float* __restrict__ pbx,
                                                   int b0) {
    int bg = blockIdx.x + b0 * GG;
    int b  = bg >> 7;
    GTC q = d_gt[bg];
    if (!(q.flags & 1)) return;

    int tid = threadIdx.x, lane = tid & 31, wid = tid >> 5;

    __shared__ float    s_av[NN];          // 33.6 KB
    __shared__ u64      s_cmax[256];
    __shared__ u64      s_rm[256];
    __shared__ u64      s_red[8];
    __shared__ unsigned s_chosen[8];

    const float4* am4 = (const float4*)(d_am + (size_t)bg * NN);
    float4*       av4 = (float4*)s_av;
    bool fb = (d_cnt[bg] == 0) && (q.flags & 2);

    u64 cm = 0;
    for (int i = tid; i < NQ4; i += 256) {
        float4 v = am4[i];
        av4[i] = v;
        float m4 = fmaxf(fmaxf(v.x, v.y), fmaxf(v.z, v.w));
        int j = (v.x == m4) ? 0 : ((v.y == m4) ? 1 : ((v.z == m4) ? 2 : 3));
        u64 key = ((u64)__float_as_uint(m4) << 32) | (unsigned)(16384 - (4 * i + j));
        if (key > cm) cm = key;
    }
    s_rm[tid] = 0;

    // -------- tiny/elongated fallback (rare) --------
    if (fb) {
        __syncthreads();
        for (int r = 0; r < 8; r++) {
            u64 key = 0xFFFFFFFFFFFFFFFFull;
            for (int n = tid; n < NN; n += 256) {
                bool skip = false;
                for (int qq = 0; qq < r; qq++)
                    if (s_chosen[qq] == (unsigned)n) skip = true;
                if (!skip) {
                    float2 a = anch[n];
                    float dx = a.x - q.gx, dy = a.y - q.gy;
                    float d2 = dx * dx + dy * dy;
                    u64 k = ((u64)__float_as_uint(d2) << 32) | (unsigned)n;
                    if (k < key) key = k;
                }
            }
#pragma unroll
            for (int o = 16; o; o >>= 1) {
                u64 t = __shfl_xor_sync(0xffffffffu, key, o);
                if (t < key) key = t;
            }
            if (lane == 0) s_red[wid] = key;
            __syncthreads();
            if (wid == 0) {
                u64 v = (lane < 8) ? s_red[lane] : 0xFFFFFFFFFFFFFFFFull;
#pragma unroll
                for (int o = 4; o; o >>= 1) {
                    u64 t = __shfl_xor_sync(0xffffffffu, v, o);
                    if (t < v) v = t;
                }
                if (lane == 0) s_chosen[r] = (unsigned)(v & 0xffffffffu);
            }
            __syncthreads();
            unsigned nw = s_chosen[r];
            if (r < q.fbk && (int)(nw & 255u) == tid) {
                int n = (int)nw;
                float2 a = anch[n];
                float dxa = a.x - q.gx, dya = a.y - q.gy;
                size_t base = (size_t)(b * NN + n) * 5;
                float dxp = pbx[base] - q.gx, dyp = pbx[base + 1] - q.gy;
                float t = (dxp * dxp + dyp * dyp) * q.inv_s2;
                float x = __expf(-t) + EPSF;
                float x2 = x * x; float x6 = x2 * x2 * x2;
                float wv = (pbx[base + 4] - q.gth) + HPI_F;
                wv -= PI_F * floorf(wv * IPI_F);
                float wr = fabsf(wv - HPI_F);
                float c = (dxa * dxa + dya * dya) * q.inv_sc2;
                float sg = 1.f / (1.f + __expf(-ps[base + q.lbl]));
                sg = fminf(fmaxf(sg, EPSF), 1.f);
                float lcl = 0.5f * __logf(sg + EPSF);
                float v = fmaxf(q.factor * x6 * __expf(lcl - 1.5f * wr - c), 0.f);
                s_av[n] = v;
                u64 bk = ((u64)__float_as_uint(v) << 32) | (unsigned)(127 - (bg & 127));
                atomicMax((u64*)(d_best + b * NN + n), bk);
            }
            __syncthreads();
        }
        // recompute column maxima after patches
        cm = 0;
        for (int i = tid; i < NQ4; i += 256) {
            float4 v = av4[i];
            float m4 = fmaxf(fmaxf(v.x, v.y), fmaxf(v.z, v.w));
            int j = (v.x == m4) ? 0 : ((v.y == m4) ? 1 : ((v.z == m4) ? 2 : 3));
            u64 key = ((u64)__float_as_uint(m4) << 32) | (unsigned)(16384 - (4 * i + j));
            if (key > cm) cm = key;
        }
    }

    s_cmax[tid] = cm;
    __syncthreads();
    if (wid != 0) return;

    // -------- warp-0-only 18-round extraction --------
    u64 myk[8];
#pragma unroll
    for (int j2 = 0; j2 < 8; j2++) myk[j2] = s_cmax[lane * 8 + j2];
    u64 topkey = 0;

    for (int r = 0; r < MAXTK; r++) {
        u64 m = myk[0];
#pragma unroll
        for (int j2 = 1; j2 < 8; j2++) if (myk[j2] > m) m = myk[j2];
        unsigned hi = (unsigned)(m >> 32);
        unsigned hmax = __reduce_max_sync(0xffffffffu, hi);
        unsigned lo = (hi == hmax) ? (unsigned)m : 0u;
        unsigned lmax = __reduce_max_sync(0xffffffffu, lo);
        if (lane == r) topkey = ((u64)hmax << 32) | lmax;

        int bn = 16384 - (int)lmax;
        int bi = bn >> 2;
        int c  = bi & 255;
        int mi = ((bi >> 8) << 2) | (bn & 3);
        if (lane == 0) s_rm[c] |= (1ull << mi);
        __syncwarp();
        u64 rmm = s_rm[c];
        int nv = (c < (NQ4 & 255)) ? 36 : 32;
        u64 nk = 0;
        {
            int mm = lane;
            if (!((rmm >> mm) & 1ull)) {
                int n2 = 4 * (c + (mm >> 2) * 256) + (mm & 3);
                nk = ((u64)__float_as_uint(s_av[n2]) << 32) | (unsigned)(16384 - n2);
            }
            if (nv == 36 && lane < 4) {
                int mm2 = 32 + lane;
                if (!((rmm >> mm2) & 1ull)) {
                    int n2 = 4 * (c + (mm2 >> 2) * 256) + (mm2 & 3);
                    u64 k2 = ((u64)__float_as_uint(s_av[n2]) << 32) | (unsigned)(16384 - n2);
                    if (k2 > nk) nk = k2;
                }
            }
        }
        unsigned h2 = (unsigned)(nk >> 32);
        unsigned hm2 = __reduce_max_sync(0xffffffffu, h2);
        unsigned lo2 = (h2 == hm2) ? (unsigned)nk : 0u;
        unsigned lm2 = __reduce_max_sync(0xffffffffu, lo2);
        u64 newmax = ((u64)hm2 << 32) | lm2;
        if (lane == (c >> 3)) {
            switch (c & 7) {
                case 0: myk[0] = newmax; break;
                case 1: myk[1] = newmax; break;
                case 2: myk[2] = newmax; break;
                case 3: myk[3] = newmax; break;
                case 4: myk[4] = newmax; break;
                case 5: myk[5] = newmax; break;
                case 6: myk[6] = newmax; break;
                case 7: myk[7] = newmax; break;
            }
        }
    }

    // -------- epilogue (warp 0) --------
    {
        float val = 0.f; unsigned nj = 0; float ovj = 0.f;
        if (lane < MAXTK) {
            val = __uint_as_float((unsigned)(topkey >> 32));
            nj = 16384u - (unsigned)(topkey & 0xffffffffull);
            size_t base = (size_t)(b * NN + nj) * 5;
            float dx = pbx[base] - q.gx, dy = pbx[base + 1] - q.gy;
            float t = (dx * dx + dy * dy) * q.inv_s2;
            ovj = fminf(fmaxf(__expf(-t), 0.f), 1.f);
        }
        float s = ovj;
#pragma unroll
        for (int o = 16; o; o >>= 1) s += __shfl_xor_sync(0xffffffffu, s, o);
        float dk = rintf(s);
        dk = fmaxf(dk, 1.f);
        dk = fminf(dk, (float)q.budget);
        int dyn = (int)dk;
        bool sel = (lane < MAXTK) && (val > EPSF) && (lane < dyn);
        unsigned bal = __ballot_sync(0xffffffffu, sel);
        if (bal) {
            int first = __ffs(bal) - 1;
            float maxalign = __shfl_sync(0xffffffffu, val, first);
            float mo = sel ? ovj : 0.f;
#pragma unroll
            for (int o = 16; o; o >>= 1) mo = fmaxf(mo, __shfl_xor_sync(0xffffffffu, mo, o));
            if (sel) {
                float nv2 = val * mo / (maxalign + EPSF);
                atomicMax(d_norm + b * NN + nj, __float_as_int(nv2));
                d_pos[b * NN + nj] = 1;
            }
        }
    }
}

// ---------------------------------------------------------------------------
// D: half-range output writer. idx in [b0*NN, (b0+nb)*NN).
// ---------------------------------------------------------------------------
__global__ __launch_bounds__(256) void out_kernel(const int* __restrict__ gl,
                                                  const float* __restrict__ gb,
                                                  float* __restrict__ out,
                                                  int b0, int nb) {
    int li = blockIdx.x * 256 + threadIdx.x;
    if (li >= nb * NN) return;
    int idx = b0 * NN + li;
    int b = idx / NN;
    u64 key = d_best[idx];
    int g = 127 - (int)(key & 0xffffffffull);
    bool pos = d_pos[idx] != 0;
    int lab = gl[b * GG + g];
    out[idx] = pos ? (float)lab : 5.f;
    const float* gp = gb + (size_t)(b * GG + g) * 5;
    float* ob = out + BN + (size_t)idx * 5;
    ob[0] = gp[0]; ob[1] = gp[1]; ob[2] = gp[2]; ob[3] = gp[3]; ob[4] = gp[4];
    float nv = __int_as_float(d_norm[idx]);
    float* os = out + (size_t)BN * 6 + (size_t)idx * 5;
#pragma unroll
    for (int c = 0; c < 5; c++) os[c] = (pos && c == lab) ? nv : 0.f;
    out[(size_t)BN * 11 + idx] = pos ? 1.f : 0.f;
}

// ---------------------------------------------------------------------------
extern "C" void kernel_launch(void* const* d_in, const int* in_sizes, int n_in,
                              void* d_out, int out_size) {
    const float* ps  = (const float*)d_in[0];
    const float* pbx = (const float*)d_in[1];
    const float* ap  = (const float*)d_in[2];
    const int*   gl  = (const int*)d_in[3];
    const float* gbx = (const float*)d_in[4];
    const float* mg  = (const float*)d_in[5];
    float* out = (float*)d_out;

    // One-time handle init (first call = correctness run, outside capture).
    // Subsequent calls issue the identical op sequence every time.
    static cudaStream_t s2 = 0;
    static cudaEvent_t evA = 0, evB = 0;
    if (s2 == 0) {
        cudaStreamCreateWithFlags(&s2, cudaStreamNonBlocking);
        cudaEventCreateWithFlags(&evA, cudaEventDisableTiming);
        cudaEventCreateWithFlags(&evB, cudaEventDisableTiming);
    }

    const int H0 = BSPLIT, H1 = BB - BSPLIT;

    // default stream: prep + first half
    prep_gt<<<(BGT + 255) / 256, 256>>>(gl, gbx, mg);
    dim3 ga0((NN + 511) / 512, H0);
    pair_kernel<<<ga0, 512>>>((const float2*)ap, ps, pbx, 0);
    cudaEventRecord(evA, 0);

    // side stream: second half (forked after first-half pair)
    cudaStreamWaitEvent(s2, evA, 0);
    dim3 ga1((NN + 511) / 512, H1);
    pair_kernel<<<ga1, 512, 0, s2>>>((const float2*)ap, ps, pbx, H0);
    topk_kernel<<<H1 * GG, 256, 0, s2>>>((const float2*)ap, ps, pbx, H0);
    out_kernel<<<(H1 * NN + 255) / 256, 256, 0, s2>>>(gl, gbx, out, H0, H1);
    cudaEventRecord(evB, s2);

    // default stream: first-half topk/out, overlapping with side stream
    topk_kernel<<<H0 * GG, 256>>>((const float2*)ap, ps, pbx, 0);
    out_kernel<<<(H0 * NN + 255) / 256, 256>>>(gl, gbx, out, 0, H0);

    // rejoin
    cudaStreamWaitEvent(0, evB, 0);
}

// round 14
// speedup vs baseline: 1.0458x; 1.0458x over previous
#include <cuda_runtime.h>
#include <math.h>

#define BB 16
#define NN 8400
#define GG 128
#define NCL 5
#define BN (BB*NN)      // 134400
#define BGT (BB*GG)     // 2048
#define NQ4 (NN/4)      // 2100 float4s per row
#define MAXTK 18
#define EPSF 1e-9f
#define HPI_F 1.57079632679489662f
#define PI_F  3.14159265358979323f
#define IPI_F 0.318309886183790672f
#define TOPK_DSM (2*NN*4 + 2*256*8 + 2*256*8)   // 75392 B

typedef unsigned long long u64;

struct GTC {
    float gx, gy, ct, st;
    float w15, h15, inv_s2, inv_sc2;
    float factor, gth;
    int budget, fbk, flags, lbl;
    float pad0, pad1;
};

__device__ GTC           d_gt[BGT];
__device__ float         d_am[(size_t)BGT * NN];  // [b][g][n]
__device__ u64           d_best[BN];              // (val<<32)|(127-g)
__device__ int           d_norm[BN];
__device__ unsigned char d_pos[BN];
__device__ int           d_cnt[BGT];              // nonzero in-center flag

// ---------------------------------------------------------------------------
__global__ __launch_bounds__(256) void prep_gt(const int* __restrict__ gl,
                                               const float* __restrict__ gb,
                                               const float* __restrict__ mg) {
    int bg = blockIdx.x * 256 + threadIdx.x;
    if (bg >= BGT) return;
    const float* g = gb + (size_t)bg * 5;
    float gx = g[0], gy = g[1], w = g[2], h = g[3], th = g[4];
    float wc = fmaxf(w, EPSF), hc = fmaxf(h, EPSF);
    float area = wc * hc;
    float ar = fmaxf(wc / hc, hc / wc);
    float sev = fminf(fmaxf((0.01f - area) / (0.01f + EPSF), 0.f), 1.f);
    int te = (int)ceilf(sev * 4.f);
    int el = (ar >= 4.f) ? 1 : 0;
    GTC q;
    q.gx = gx; q.gy = gy;
    q.ct = cosf(-th); q.st = sinf(-th);
    q.w15 = w * 1.5f; q.h15 = h * 1.5f;
    float sc = sqrtf(w * h);
    float is = 1.f / (sc + 1e-6f);         q.inv_s2  = is * is;
    float isc = 1.f / (sc * 1.5f + 1e-6f); q.inv_sc2 = isc * isc;
    float strength = fminf(fmaxf((ar - 4.f) / (4.f + EPSF), 0.f), 1.f);
    q.factor = (1.f + sev * (4.f / 13.f)) * (1.f + 0.25f * strength);
    q.gth = th;
    q.budget = 13 + te + el;
    q.fbk = te + el + 3;
    int fl = (mg[bg] > 0.f) ? 1 : 0;
    if ((area < 0.01f) || (ar >= 4.f)) fl |= 2;
    q.flags = fl;
    q.lbl = gl[bg];
    if (!(fl & 1)) q.factor = 0.f;   // masked GT: body yields exactly 0
    q.pad0 = 0.f; q.pad1 = 0.f;
    d_gt[bg] = q;
    d_cnt[bg] = 0;
}

// ---------------------------------------------------------------------------
// A (R11, pinned): block = (512-anchor tile, b), 512 threads, 1 anchor/thread.
// ---------------------------------------------------------------------------
__global__ __launch_bounds__(512) void pair_kernel(const float2* __restrict__ anch,
                                                   const float* __restrict__ ps,
                                                   const float* __restrict__ pbx) {
    int b   = blockIdx.y;
    int tid = threadIdx.x;
    int n   = blockIdx.x * 512 + tid;

    __shared__ GTC           s_gt[GG];     // 8 KB
    __shared__ unsigned char s_any[GG];

    {
        const float4* src = (const float4*)(d_gt + b * GG);
        float4*       dst = (float4*)s_gt;
        dst[tid] = src[tid];
        if (tid < GG) s_any[tid] = 0;
    }
    __syncthreads();

    bool valid = (n < NN);
    float ax = 0.f, ay = 0.f, px = 0.f, py = 0.f, pt = 0.f;
    float l0 = 0.f, l1 = 0.f, l2 = 0.f, l3 = 0.f, l4 = 0.f;
    if (valid) {
        float2 a = anch[n];
        ax = a.x; ay = a.y;
        size_t base = (size_t)(b * NN + n) * 5;
        px = pbx[base]; py = pbx[base + 1]; pt = pbx[base + 4];
#define LC(d, i) { float sg = 1.f/(1.f+__expf(-ps[base+(i)])); \
                   sg = fminf(fmaxf(sg, EPSF), 1.f); d = 0.5f*__logf(sg+EPSF); }
        LC(l0,0) LC(l1,1) LC(l2,2) LC(l3,3) LC(l4,4)
#undef LC
    }

    float bv = 0.f;
    int   bgi = 0;
    float* amp = d_am + (size_t)b * GG * NN + n;

#pragma unroll 2
    for (int g = 0; g < GG; g++) {
        GTC q = s_gt[g];
        float dxa = ax - q.gx, dya = ay - q.gy;
        float lx = dxa * q.ct - dya * q.st;
        float ly = dxa * q.st + dya * q.ct;
        bool in = valid && (fabsf(lx) < q.w15) && (fabsf(ly) < q.h15);

        float dxp = px - q.gx, dyp = py - q.gy;
        float t = (dxp * dxp + dyp * dyp) * q.inv_s2;
        float x = __expf(-t) + EPSF;
        float x2 = x * x; float x6 = x2 * x2 * x2;
        float wv = (pt - q.gth) + HPI_F;
        wv -= PI_F * floorf(wv * IPI_F);
        float wr = fabsf(wv - HPI_F);
        float c = (dxa * dxa + dya * dya) * q.inv_sc2;
        int lb = q.lbl;
        float lcl = lb == 0 ? l0 : (lb == 1 ? l1 : (lb == 2 ? l2 : (lb == 3 ? l3 : l4)));
        float val = fmaxf(q.factor * x6 * __expf(lcl - 1.5f * wr - c), 0.f);
        float vv = in ? val : 0.f;

        if (in) s_any[g] = 1;
        if (valid) amp[(size_t)g * NN] = vv;
        if (vv > bv) { bv = vv; bgi = g; }
    }
    __syncthreads();
    if (tid < GG && s_any[tid]) atomicOr(&d_cnt[b * GG + tid], 1);
    if (valid) {
        int idx = b * NN + n;
        d_best[idx] = ((u64)__float_as_uint(bv) << 32) | (unsigned)(127 - bgi);
        d_norm[idx] = 0;
        d_pos[idx]  = 0;
    }
}

// ---------------------------------------------------------------------------
// 18-round extraction + epilogue for one row, executed by ONE full warp.
// ---------------------------------------------------------------------------
__device__ __forceinline__ void extract18(const GTC& q, int b, int bg,
                                          const float* s_av, const u64* s_cmax,
                                          u64* s_rm, const float* __restrict__ pbx) {
    int lane = threadIdx.x & 31;
    u64 myk[8];
#pragma unroll
    for (int j2 = 0; j2 < 8; j2++) myk[j2] = s_cmax[lane * 8 + j2];
    u64 topkey = 0;

    for (int r = 0; r < MAXTK; r++) {
        u64 m = myk[0];
#pragma unroll
        for (int j2 = 1; j2 < 8; j2++) if (myk[j2] > m) m = myk[j2];
        unsigned hi = (unsigned)(m >> 32);
        unsigned hmax = __reduce_max_sync(0xffffffffu, hi);
        unsigned lo = (hi == hmax) ? (unsigned)m : 0u;
        unsigned lmax = __reduce_max_sync(0xffffffffu, lo);
        if (lane == r) topkey = ((u64)hmax << 32) | lmax;

        int bn = 16384 - (int)lmax;
        int bi = bn >> 2;
        int c  = bi & 255;
        int mi = ((bi >> 8) << 2) | (bn & 3);
        if (lane == 0) s_rm[c] |= (1ull << mi);
        __syncwarp();
        u64 rmm = s_rm[c];
        int nv = (c < (NQ4 & 255)) ? 36 : 32;   // columns < 52 hold 9 float4s
        u64 nk = 0;
        {
            int mm = lane;
            if (!((rmm >> mm) & 1ull)) {
                int n2 = 4 * (c + (mm >> 2) * 256) + (mm & 3);
                nk = ((u64)__float_as_uint(s_av[n2]) << 32) | (unsigned)(16384 - n2);
            }
            if (nv == 36 && lane < 4) {
                int mm2 = 32 + lane;
                if (!((rmm >> mm2) & 1ull)) {
                    int n2 = 4 * (c + (mm2 >> 2) * 256) + (mm2 & 3);
                    u64 k2 = ((u64)__float_as_uint(s_av[n2]) << 32) | (unsigned)(16384 - n2);
                    if (k2 > nk) nk = k2;
                }
            }
        }
        unsigned h2 = (unsigned)(nk >> 32);
        unsigned hm2 = __reduce_max_sync(0xffffffffu, h2);
        unsigned lo2 = (h2 == hm2) ? (unsigned)nk : 0u;
        unsigned lm2 = __reduce_max_sync(0xffffffffu, lo2);
        u64 newmax = ((u64)hm2 << 32) | lm2;
        if (lane == (c >> 3)) {
            switch (c & 7) {
                case 0: myk[0] = newmax; break;
                case 1: myk[1] = newmax; break;
                case 2: myk[2] = newmax; break;
                case 3: myk[3] = newmax; break;
                case 4: myk[4] = newmax; break;
                case 5: myk[5] = newmax; break;
                case 6: myk[6] = newmax; break;
                case 7: myk[7] = newmax; break;
            }
        }
    }

    // epilogue
    float val = 0.f; unsigned nj = 0; float ovj = 0.f;
    if (lane < MAXTK) {
        val = __uint_as_float((unsigned)(topkey >> 32));
        nj = 16384u - (unsigned)(topkey & 0xffffffffull);
        size_t base = (size_t)(b * NN + nj) * 5;
        float dx = pbx[base] - q.gx, dy = pbx[base + 1] - q.gy;
        float t = (dx * dx + dy * dy) * q.inv_s2;
        ovj = fminf(fmaxf(__expf(-t), 0.f), 1.f);
    }
    float s = ovj;
#pragma unroll
    for (int o = 16; o; o >>= 1) s += __shfl_xor_sync(0xffffffffu, s, o);
    float dk = rintf(s);
    dk = fmaxf(dk, 1.f);
    dk = fminf(dk, (float)q.budget);
    int dyn = (int)dk;
    bool sel = (lane < MAXTK) && (val > EPSF) && (lane < dyn);
    unsigned bal = __ballot_sync(0xffffffffu, sel);
    if (bal) {
        int first = __ffs(bal) - 1;
        float maxalign = __shfl_sync(0xffffffffu, val, first);
        float mo = sel ? ovj : 0.f;
#pragma unroll
        for (int o = 16; o; o >>= 1) mo = fmaxf(mo, __shfl_xor_sync(0xffffffffu, mo, o));
        if (sel) {
            float nv2 = val * mo / (maxalign + EPSF);
            atomicMax(d_norm + b * NN + nj, __float_as_int(nv2));
            d_pos[b * NN + nj] = 1;
        }
    }
}

// ---------------------------------------------------------------------------
// Block-wide fallback for one row (rare). Returns recomputed column max.
// ---------------------------------------------------------------------------
__device__ u64 do_fallback(const GTC& q, int bg, float* s_av,
                           const float2* __restrict__ anch,
                           const float* __restrict__ ps,
                           const float* __restrict__ pbx,
                           u64* s_red, unsigned* s_chosen) {
    int tid = threadIdx.x, lane = tid & 31, wid = tid >> 5;
    int b = bg >> 7;
    __syncthreads();
    for (int r = 0; r < 8; r++) {
        u64 key = 0xFFFFFFFFFFFFFFFFull;
        for (int n = tid; n < NN; n += 256) {
            bool skip = false;
            for (int qq = 0; qq < r; qq++)
                if (s_chosen[qq] == (unsigned)n) skip = true;
            if (!skip) {
                float2 a = anch[n];
                float dx = a.x - q.gx, dy = a.y - q.gy;
                float d2 = dx * dx + dy * dy;
                u64 k = ((u64)__float_as_uint(d2) << 32) | (unsigned)n;
                if (k < key) key = k;
            }
        }
#pragma unroll
        for (int o = 16; o; o >>= 1) {
            u64 t = __shfl_xor_sync(0xffffffffu, key, o);
            if (t < key) key = t;
        }
        if (lane == 0) s_red[wid] = key;
        __syncthreads();
        if (wid == 0) {
            u64 v = (lane < 8) ? s_red[lane] : 0xFFFFFFFFFFFFFFFFull;
#pragma unroll
            for (int o = 4; o; o >>= 1) {
                u64 t = __shfl_xor_sync(0xffffffffu, v, o);
                if (t < v) v = t;
            }
            if (lane == 0) s_chosen[r] = (unsigned)(v & 0xffffffffu);
        }
        __syncthreads();
        unsigned nw = s_chosen[r];
        if (r < q.fbk && (int)(nw & 255u) == tid) {
            int n = (int)nw;
            float2 a = anch[n];
            float dxa = a.x - q.gx, dya = a.y - q.gy;
            size_t base = (size_t)(b * NN + n) * 5;
            float dxp = pbx[base] - q.gx, dyp = pbx[base + 1] - q.gy;
            float t = (dxp * dxp + dyp * dyp) * q.inv_s2;
            float x = __expf(-t) + EPSF;
            float x2 = x * x; float x6 = x2 * x2 * x2;
            float wv = (pbx[base + 4] - q.gth) + HPI_F;
            wv -= PI_F * floorf(wv * IPI_F);
            float wr = fabsf(wv - HPI_F);
            float c = (dxa * dxa + dya * dya) * q.inv_sc2;
            float sg = 1.f / (1.f + __expf(-ps[base + q.lbl]));
            sg = fminf(fmaxf(sg, EPSF), 1.f);
            float lcl = 0.5f * __logf(sg + EPSF);
            float v = fmaxf(q.factor * x6 * __expf(lcl - 1.5f * wr - c), 0.f);
            s_av[n] = v;
            u64 bk = ((u64)__float_as_uint(v) << 32) | (unsigned)(127 - (bg & 127));
            atomicMax((u64*)(d_best + b * NN + n), bk);
        }
        __syncthreads();
    }
    // recompute column max
    u64 cm = 0;
    const float4* av4 = (const float4*)s_av;
    for (int i = tid; i < NQ4; i += 256) {
        float4 v = av4[i];
        float m4 = fmaxf(fmaxf(v.x, v.y), fmaxf(v.z, v.w));
        int j = (v.x == m4) ? 0 : ((v.y == m4) ? 1 : ((v.z == m4) ? 2 : 3));
        u64 key = ((u64)__float_as_uint(m4) << 32) | (unsigned)(16384 - (4 * i + j));
        if (key > cm) cm = key;
    }
    return cm;
}

// ---------------------------------------------------------------------------
// B: block = 2 rows (2i, 2i+1). Copy both rows + colmax, fallbacks, then
// warp 0 extracts row A concurrently with warp 1 extracting row B.
// ---------------------------------------------------------------------------
__global__ __launch_bounds__(256) void topk_kernel(const float2* __restrict__ anch,
                                                   const float* __restrict__ ps,
                                                   const float* __restrict__ pbx) {
    int rA = blockIdx.x * 2;
    int rB = rA + 1;
    GTC qA = d_gt[rA];
    GTC qB = d_gt[rB];
    bool actA = (qA.flags & 1) != 0;
    bool actB = (qB.flags & 1) != 0;
    if (!actA && !actB) return;

    int tid = threadIdx.x, wid = tid >> 5;

    extern __shared__ char dynsm[];
    float* s_avA   = (float*)dynsm;                       // NN floats
    float* s_avB   = s_avA + NN;                          // NN floats
    u64*   s_cmax  = (u64*)(dynsm + 2 * NN * 4);          // [2][256]
    u64*   s_rm    = s_cmax + 512;                        // [2][256]
    __shared__ u64      s_red[8];
    __shared__ unsigned s_chosen[8];

    const float4* amA = (const float4*)(d_am + (size_t)rA * NN);
    const float4* amB = (const float4*)(d_am + (size_t)rB * NN);
    float4* avA4 = (float4*)s_avA;
    float4* avB4 = (float4*)s_avB;

    u64 cmA = 0, cmB = 0;
    for (int i = tid; i < NQ4; i += 256) {
        if (actA) {
            float4 v = amA[i];
            avA4[i] = v;
            float m4 = fmaxf(fmaxf(v.x, v.y), fmaxf(v.z, v.w));
            int j = (v.x == m4) ? 0 : ((v.y == m4) ? 1 : ((v.z == m4) ? 2 : 3));
            u64 key = ((u64)__float_as_uint(m4) << 32) | (unsigned)(16384 - (4 * i + j));
            if (key > cmA) cmA = key;
        }
        if (actB) {
            float4 v = amB[i];
            avB4[i] = v;
            float m4 = fmaxf(fmaxf(v.x, v.y), fmaxf(v.z, v.w));
            int j = (v.x == m4) ? 0 : ((v.y == m4) ? 1 : ((v.z == m4) ? 2 : 3));
            u64 key = ((u64)__float_as_uint(m4) << 32) | (unsigned)(16384 - (4 * i + j));
            if (key > cmB) cmB = key;
        }
    }
    s_rm[tid] = 0;
    s_rm[256 + tid] = 0;

    bool fbA = actA && (d_cnt[rA] == 0) && (qA.flags & 2);
    bool fbB = actB && (d_cnt[rB] == 0) && (qB.flags & 2);
    if (fbA) cmA = do_fallback(qA, rA, s_avA, anch, ps, pbx, s_red, s_chosen);
    if (fbB) cmB = do_fallback(qB, rB, s_avB, anch, ps, pbx, s_red, s_chosen);

    s_cmax[tid] = cmA;
    s_cmax[256 + tid] = cmB;
    __syncthreads();

    if (wid == 0) {
        if (actA) extract18(qA, rA >> 7, rA, s_avA, s_cmax, s_rm, pbx);
    } else if (wid == 1) {
        if (actB) extract18(qB, rB >> 7, rB, s_avB, s_cmax + 256, s_rm + 256, pbx);
    }
}

// ---------------------------------------------------------------------------
__global__ __launch_bounds__(256) void out_kernel(const int* __restrict__ gl,
                                                  const float* __restrict__ gb,
                                                  float* __restrict__ out) {
    int idx = blockIdx.x * 256 + threadIdx.x;
    if (idx >= BN) return;
    int b = idx / NN;
    u64 key = d_best[idx];
    int g = 127 - (int)(key & 0xffffffffull);
    bool pos = d_pos[idx] != 0;
    int lab = gl[b * GG + g];
    out[idx] = pos ? (float)lab : 5.f;
    const float* gp = gb + (size_t)(b * GG + g) * 5;
    float* ob = out + BN + (size_t)idx * 5;
    ob[0] = gp[0]; ob[1] = gp[1]; ob[2] = gp[2]; ob[3] = gp[3]; ob[4] = gp[4];
    float nv = __int_as_float(d_norm[idx]);
    float* os = out + (size_t)BN * 6 + (size_t)idx * 5;
#pragma unroll
    for (int c = 0; c < 5; c++) os[c] = (pos && c == lab) ? nv : 0.f;
    out[(size_t)BN * 11 + idx] = pos ? 1.f : 0.f;
}

// ---------------------------------------------------------------------------
extern "C" void kernel_launch(void* const* d_in, const int* in_sizes, int n_in,
                              void* d_out, int out_size) {
    const float* ps  = (const float*)d_in[0];
    const float* pbx = (const float*)d_in[1];
    const float* ap  = (const float*)d_in[2];
    const int*   gl  = (const int*)d_in[3];
    const float* gbx = (const float*)d_in[4];
    const float* mg  = (const float*)d_in[5];

    cudaFuncSetAttribute(topk_kernel,
                         cudaFuncAttributeMaxDynamicSharedMemorySize, TOPK_DSM);

    prep_gt<<<(BGT + 255) / 256, 256>>>(gl, gbx, mg);
    dim3 ga((NN + 511) / 512, BB);
    pair_kernel<<<ga, 512>>>((const float2*)ap, ps, pbx);
    topk_kernel<<<BGT / 2, 256, TOPK_DSM>>>((const float2*)ap, ps, pbx);
    out_kernel<<<(BN + 255) / 256, 256>>>(gl, gbx, (float*)d_out);
}

// round 15
// speedup vs baseline: 1.2071x; 1.1542x over previous
#include <cuda_runtime.h>
#include <math.h>

#define BB 16
#define NN 8400
#define GG 128
#define NCL 5
#define BN (BB*NN)      // 134400
#define BGT (BB*GG)     // 2048
#define NQ4 (NN/4)      // 2100 float4s per row
#define MAXTK 18
#define EPSF 1e-9f
#define HPI_F 1.57079632679489662f
#define PI_F  3.14159265358979323f
#define IPI_F 0.318309886183790672f

typedef unsigned long long u64;

// Field order matters: pair's g-loop touches only the first 3 float4s.
struct GTC {
    float gx, gy, ct, st;          // f4 #0
    float w15, h15, s6, inv_sc2;   // f4 #1   s6 = 6*inv_s2
    float lf, gth; int lbl; float inv_s2;  // f4 #2   lf = log(factor), -inf if masked
    int budget, fbk, flags, pad;   // f4 #3  (topk-only)
};

__device__ GTC           d_gt[BGT];
__device__ float         d_am[(size_t)BGT * NN];  // [b][g][n]
__device__ u64           d_best[BN];              // (val<<32)|(127-g)
__device__ int           d_norm[BN];
__device__ unsigned char d_pos[BN];
__device__ int           d_cnt[BGT];              // nonzero in-center flag

// ---------------------------------------------------------------------------
__global__ __launch_bounds__(256) void prep_gt(const int* __restrict__ gl,
                                               const float* __restrict__ gb,
                                               const float* __restrict__ mg) {
    int bg = blockIdx.x * 256 + threadIdx.x;
    if (bg >= BGT) return;
    const float* g = gb + (size_t)bg * 5;
    float gx = g[0], gy = g[1], w = g[2], h = g[3], th = g[4];
    float wc = fmaxf(w, EPSF), hc = fmaxf(h, EPSF);
    float area = wc * hc;
    float ar = fmaxf(wc / hc, hc / wc);
    float sev = fminf(fmaxf((0.01f - area) / (0.01f + EPSF), 0.f), 1.f);
    int te = (int)ceilf(sev * 4.f);
    int el = (ar >= 4.f) ? 1 : 0;
    GTC q;
    q.gx = gx; q.gy = gy;
    q.ct = cosf(-th); q.st = sinf(-th);
    q.w15 = w * 1.5f; q.h15 = h * 1.5f;
    float sc = sqrtf(w * h);
    float is = 1.f / (sc + 1e-6f);
    q.inv_s2 = is * is;
    q.s6 = 6.f * q.inv_s2;
    float isc = 1.f / (sc * 1.5f + 1e-6f);
    q.inv_sc2 = isc * isc;
    float strength = fminf(fmaxf((ar - 4.f) / (4.f + EPSF), 0.f), 1.f);
    float factor = (1.f + sev * (4.f / 13.f)) * (1.f + 0.25f * strength);
    q.gth = th;
    q.budget = 13 + te + el;
    q.fbk = te + el + 3;
    int fl = (mg[bg] > 0.f) ? 1 : 0;
    if ((area < 0.01f) || (ar >= 4.f)) fl |= 2;
    q.flags = fl;
    q.lbl = gl[bg];
    if (!(fl & 1)) factor = 0.f;       // masked GT: lf = -inf -> body yields 0
    q.lf = __logf(factor);
    q.pad = 0;
    d_gt[bg] = q;
    d_cnt[bg] = 0;
}

// ---------------------------------------------------------------------------
// A: block = (512-anchor tile, b), 512 threads, 1 anchor/thread, 32 warps/SM.
// Straight-line g-loop, single-exp body, 3 LDS.128/iteration.
// ---------------------------------------------------------------------------
__global__ __launch_bounds__(512) void pair_kernel(const float2* __restrict__ anch,
                                                   const float* __restrict__ ps,
                                                   const float* __restrict__ pbx) {
    int b   = blockIdx.y;
    int tid = threadIdx.x;
    int n   = blockIdx.x * 512 + tid;

    __shared__ GTC           s_gt[GG];     // 8 KB
    __shared__ unsigned char s_any[GG];

    {
        const float4* src = (const float4*)(d_gt + b * GG);
        float4*       dst = (float4*)s_gt;
        dst[tid] = src[tid];
        if (tid < GG) s_any[tid] = 0;
    }
    __syncthreads();

    bool valid = (n < NN);
    float ax = 0.f, ay = 0.f, px = 0.f, py = 0.f, pt = 0.f;
    float l0 = 0.f, l1 = 0.f, l2 = 0.f, l3 = 0.f, l4 = 0.f;
    if (valid) {
        float2 a = anch[n];
        ax = a.x; ay = a.y;
        size_t base = (size_t)(b * NN + n) * 5;
        px = pbx[base]; py = pbx[base + 1]; pt = pbx[base + 4];
#define LC(d, i) { float sg = 1.f/(1.f+__expf(-ps[base+(i)])); \
                   sg = fminf(fmaxf(sg, EPSF), 1.f); d = 0.5f*__logf(sg+EPSF); }
        LC(l0,0) LC(l1,1) LC(l2,2) LC(l3,3) LC(l4,4)
#undef LC
    }

    float bv = 0.f;
    int   bgi = 0;
    float* amp = d_am + (size_t)b * GG * NN + n;

#pragma unroll 2
    for (int g = 0; g < GG; g++) {
        GTC q = s_gt[g];
        float dxa = ax - q.gx, dya = ay - q.gy;
        float lx = dxa * q.ct - dya * q.st;
        float ly = dxa * q.st + dya * q.ct;
        bool in = valid && (fabsf(lx) < q.w15) && (fabsf(ly) < q.h15);

        float dxp = px - q.gx, dyp = py - q.gy;
        float t6 = (dxp * dxp + dyp * dyp) * q.s6;
        float wv = (pt - q.gth) + HPI_F;
        wv -= PI_F * floorf(wv * IPI_F);
        float wr = fabsf(wv - HPI_F);
        float c = (dxa * dxa + dya * dya) * q.inv_sc2;
        int lb = q.lbl;
        float lcl = lb == 0 ? l0 : (lb == 1 ? l1 : (lb == 2 ? l2 : (lb == 3 ? l3 : l4)));
        float val = fmaxf(__expf(q.lf + lcl - t6 - 1.5f * wr - c), 0.f);
        float vv = in ? val : 0.f;

        if (in) s_any[g] = 1;
        if (valid) amp[(size_t)g * NN] = vv;
        if (vv > bv) { bv = vv; bgi = g; }
    }
    __syncthreads();
    if (tid < GG && s_any[tid]) atomicOr(&d_cnt[b * GG + tid], 1);
    if (valid) {
        int idx = b * NN + n;
        d_best[idx] = ((u64)__float_as_uint(bv) << 32) | (unsigned)(127 - bgi);
        d_norm[idx] = 0;
        d_pos[idx]  = 0;
    }
}

// ---------------------------------------------------------------------------
// B (R11, pinned): block per (b,g). Copy row + column maxima in one pass,
// then warp-0-only 18-round extraction. Column c holds i = c + k*256, n=4i+j.
// ---------------------------------------------------------------------------
__global__ __launch_bounds__(256) void topk_kernel(const float2* __restrict__ anch,
                                                   const float* __restrict__ ps,
                                                   const float* __restrict__ pbx) {
    int bg = blockIdx.x;
    int b  = bg >> 7;
    GTC q = d_gt[bg];
    if (!(q.flags & 1)) return;

    int tid = threadIdx.x, lane = tid & 31, wid = tid >> 5;

    __shared__ float    s_av[NN];          // 33.6 KB
    __shared__ u64      s_cmax[256];
    __shared__ u64      s_rm[256];
    __shared__ u64      s_red[8];
    __shared__ unsigned s_chosen[8];

    const float4* am4 = (const float4*)(d_am + (size_t)bg * NN);
    float4*       av4 = (float4*)s_av;
    bool fb = (d_cnt[bg] == 0) && (q.flags & 2);

    u64 cm = 0;
    for (int i = tid; i < NQ4; i += 256) {
        float4 v = am4[i];
        av4[i] = v;
        float m4 = fmaxf(fmaxf(v.x, v.y), fmaxf(v.z, v.w));
        int j = (v.x == m4) ? 0 : ((v.y == m4) ? 1 : ((v.z == m4) ? 2 : 3));
        u64 key = ((u64)__float_as_uint(m4) << 32) | (unsigned)(16384 - (4 * i + j));
        if (key > cm) cm = key;
    }
    s_rm[tid] = 0;

    // -------- tiny/elongated fallback (rare) --------
    if (fb) {
        __syncthreads();
        for (int r = 0; r < 8; r++) {
            u64 key = 0xFFFFFFFFFFFFFFFFull;
            for (int n = tid; n < NN; n += 256) {
                bool skip = false;
                for (int qq = 0; qq < r; qq++)
                    if (s_chosen[qq] == (unsigned)n) skip = true;
                if (!skip) {
                    float2 a = anch[n];
                    float dx = a.x - q.gx, dy = a.y - q.gy;
                    float d2 = dx * dx + dy * dy;
                    u64 k = ((u64)__float_as_uint(d2) << 32) | (unsigned)n;
                    if (k < key) key = k;
                }
            }
#pragma unroll
            for (int o = 16; o; o >>= 1) {
                u64 t = __shfl_xor_sync(0xffffffffu, key, o);
                if (t < key) key = t;
            }
            if (lane == 0) s_red[wid] = key;
            __syncthreads();
            if (wid == 0) {
                u64 v = (lane < 8) ? s_red[lane] : 0xFFFFFFFFFFFFFFFFull;
#pragma unroll
                for (int o = 4; o; o >>= 1) {
                    u64 t = __shfl_xor_sync(0xffffffffu, v, o);
                    if (t < v) v = t;
                }
                if (lane == 0) s_chosen[r] = (unsigned)(v & 0xffffffffu);
            }
            __syncthreads();
            unsigned nw = s_chosen[r];
            if (r < q.fbk && (int)(nw & 255u) == tid) {
                int n = (int)nw;
                float2 a = anch[n];
                float dxa = a.x - q.gx, dya = a.y - q.gy;
                size_t base = (size_t)(b * NN + n) * 5;
                float dxp = pbx[base] - q.gx, dyp = pbx[base + 1] - q.gy;
                float t6 = (dxp * dxp + dyp * dyp) * q.s6;
                float wv = (pbx[base + 4] - q.gth) + HPI_F;
                wv -= PI_F * floorf(wv * IPI_F);
                float wr = fabsf(wv - HPI_F);
                float c = (dxa * dxa + dya * dya) * q.inv_sc2;
                float sg = 1.f / (1.f + __expf(-ps[base + q.lbl]));
                sg = fminf(fmaxf(sg, EPSF), 1.f);
                float lcl = 0.5f * __logf(sg + EPSF);
                float v = fmaxf(__expf(q.lf + lcl - t6 - 1.5f * wr - c), 0.f);
                s_av[n] = v;
                u64 bk = ((u64)__float_as_uint(v) << 32) | (unsigned)(127 - (bg & 127));
                atomicMax((u64*)(d_best + b * NN + n), bk);
            }
            __syncthreads();
        }
        // recompute column maxima after patches
        cm = 0;
        for (int i = tid; i < NQ4; i += 256) {
            float4 v = av4[i];
            float m4 = fmaxf(fmaxf(v.x, v.y), fmaxf(v.z, v.w));
            int j = (v.x == m4) ? 0 : ((v.y == m4) ? 1 : ((v.z == m4) ? 2 : 3));
            u64 key = ((u64)__float_as_uint(m4) << 32) | (unsigned)(16384 - (4 * i + j));
            if (key > cm) cm = key;
        }
    }

    s_cmax[tid] = cm;
    __syncthreads();
    if (wid != 0) return;

    // -------- warp-0-only 18-round extraction --------
    u64 myk[8];
#pragma unroll
    for (int j2 = 0; j2 < 8; j2++) myk[j2] = s_cmax[lane * 8 + j2];
    u64 topkey = 0;

    for (int r = 0; r < MAXTK; r++) {
        u64 m = myk[0];
#pragma unroll
        for (int j2 = 1; j2 < 8; j2++) if (myk[j2] > m) m = myk[j2];
        unsigned hi = (unsigned)(m >> 32);
        unsigned hmax = __reduce_max_sync(0xffffffffu, hi);
        unsigned lo = (hi == hmax) ? (unsigned)m : 0u;
        unsigned lmax = __reduce_max_sync(0xffffffffu, lo);
        if (lane == r) topkey = ((u64)hmax << 32) | lmax;

        int bn = 16384 - (int)lmax;
        int bi = bn >> 2;
        int c  = bi & 255;
        int mi = ((bi >> 8) << 2) | (bn & 3);
        if (lane == 0) s_rm[c] |= (1ull << mi);
        __syncwarp();
        u64 rmm = s_rm[c];
        int nv = (c < (NQ4 & 255)) ? 36 : 32;
        u64 nk = 0;
        {
            int mm = lane;
            if (!((rmm >> mm) & 1ull)) {
                int n2 = 4 * (c + (mm >> 2) * 256) + (mm & 3);
                nk = ((u64)__float_as_uint(s_av[n2]) << 32) | (unsigned)(16384 - n2);
            }
            if (nv == 36 && lane < 4) {
                int mm2 = 32 + lane;
                if (!((rmm >> mm2) & 1ull)) {
                    int n2 = 4 * (c + (mm2 >> 2) * 256) + (mm2 & 3);
                    u64 k2 = ((u64)__float_as_uint(s_av[n2]) << 32) | (unsigned)(16384 - n2);
                    if (k2 > nk) nk = k2;
                }
            }
        }
        unsigned h2 = (unsigned)(nk >> 32);
        unsigned hm2 = __reduce_max_sync(0xffffffffu, h2);
        unsigned lo2 = (h2 == hm2) ? (unsigned)nk : 0u;
        unsigned lm2 = __reduce_max_sync(0xffffffffu, lo2);
        u64 newmax = ((u64)hm2 << 32) | lm2;
        if (lane == (c >> 3)) {
            switch (c & 7) {
                case 0: myk[0] = newmax; break;
                case 1: myk[1] = newmax; break;
                case 2: myk[2] = newmax; break;
                case 3: myk[3] = newmax; break;
                case 4: myk[4] = newmax; break;
                case 5: myk[5] = newmax; break;
                case 6: myk[6] = newmax; break;
                case 7: myk[7] = newmax; break;
            }
        }
    }

    // -------- epilogue (warp 0) --------
    {
        float val = 0.f; unsigned nj = 0; float ovj = 0.f;
        if (lane < MAXTK) {
            val = __uint_as_float((unsigned)(topkey >> 32));
            nj = 16384u - (unsigned)(topkey & 0xffffffffull);
            size_t base = (size_t)(b * NN + nj) * 5;
            float dx = pbx[base] - q.gx, dy = pbx[base + 1] - q.gy;
            float t = (dx * dx + dy * dy) * q.inv_s2;
            ovj = fminf(fmaxf(__expf(-t), 0.f), 1.f);
        }
        float s = ovj;
#pragma unroll
        for (int o = 16; o; o >>= 1) s += __shfl_xor_sync(0xffffffffu, s, o);
        float dk = rintf(s);
        dk = fmaxf(dk, 1.f);
        dk = fminf(dk, (float)q.budget);
        int dyn = (int)dk;
        bool sel = (lane < MAXTK) && (val > EPSF) && (lane < dyn);
        unsigned bal = __ballot_sync(0xffffffffu, sel);
        if (bal) {
            int first = __ffs(bal) - 1;
            float maxalign = __shfl_sync(0xffffffffu, val, first);
            float mo = sel ? ovj : 0.f;
#pragma unroll
            for (int o = 16; o; o >>= 1) mo = fmaxf(mo, __shfl_xor_sync(0xffffffffu, mo, o));
            if (sel) {
                float nv2 = val * mo / (maxalign + EPSF);
                atomicMax(d_norm + b * NN + nj, __float_as_int(nv2));
                d_pos[b * NN + nj] = 1;
            }
        }
    }
}

// ---------------------------------------------------------------------------
__global__ __launch_bounds__(256) void out_kernel(const int* __restrict__ gl,
                                                  const float* __restrict__ gb,
                                                  float* __restrict__ out) {
    int idx = blockIdx.x * 256 + threadIdx.x;
    if (idx >= BN) return;
    int b = idx / NN;
    u64 key = d_best[idx];
    int g = 127 - (int)(key & 0xffffffffull);
    bool pos = d_pos[idx] != 0;
    int lab = gl[b * GG + g];
    out[idx] = pos ? (float)lab : 5.f;
    const float* gp = gb + (size_t)(b * GG + g) * 5;
    float* ob = out + BN + (size_t)idx * 5;
    ob[0] = gp[0]; ob[1] = gp[1]; ob[2] = gp[2]; ob[3] = gp[3]; ob[4] = gp[4];
    float nv = __int_as_float(d_norm[idx]);
    float* os = out + (size_t)BN * 6 + (size_t)idx * 5;
#pragma unroll
    for (int c = 0; c < 5; c++) os[c] = (pos && c == lab) ? nv : 0.f;
    out[(size_t)BN * 11 + idx] = pos ? 1.f : 0.f;
}

// ---------------------------------------------------------------------------
extern "C" void kernel_launch(void* const* d_in, const int* in_sizes, int n_in,
                              void* d_out, int out_size) {
    const float* ps  = (const float*)d_in[0];
    const float* pbx = (const float*)d_in[1];
    const float* ap  = (const float*)d_in[2];
    const int*   gl  = (const int*)d_in[3];
    const float* gbx = (const float*)d_in[4];
    const float* mg  = (const float*)d_in[5];

    prep_gt<<<(BGT + 255) / 256, 256>>>(gl, gbx, mg);
    dim3 ga((NN + 511) / 512, BB);
    pair_kernel<<<ga, 512>>>((const float2*)ap, ps, pbx);
    topk_kernel<<<BGT, 256>>>((const float2*)ap, ps, pbx);
    out_kernel<<<(BN + 255) / 256, 256>>>(gl, gbx, (float*)d_out);
}

// round 16
// speedup vs baseline: 1.2394x; 1.0267x over previous
#include <cuda_runtime.h>
#include <math.h>

#define BB 16
#define NN 8400
#define GG 128
#define NCL 5
#define BN (BB*NN)      // 134400
#define BGT (BB*GG)     // 2048
#define NQ4 (NN/4)      // 2100 float4s per row
#define MAXTK 18
#define EPSF 1e-9f
#define HPI_F 1.57079632679489662f
#define PI_F  3.14159265358979323f
#define IPI_F 0.318309886183790672f

typedef unsigned long long u64;

// Field order matters: pair's g-loop touches only the first 3 float4s.
struct GTC {
    float gx, gy, ct, st;          // f4 #0
    float w15, h15, s6, inv_sc2;   // f4 #1   s6 = 6*inv_s2
    float lf, gth; int lbl; float inv_s2;  // f4 #2   lf = log(factor), -inf if masked
    int budget, fbk, flags, pad;   // f4 #3  (topk-only)
};

__device__ GTC           d_gt[BGT];
__device__ float         d_am[(size_t)BGT * NN];  // [b][g][n]
__device__ u64           d_best[BN];              // (val<<32)|(127-g)
__device__ int           d_norm[BN];
__device__ unsigned char d_pos[BN];
__device__ int           d_cnt[BGT];              // nonzero in-center flag

// ---------------------------------------------------------------------------
__global__ __launch_bounds__(256) void prep_gt(const int* __restrict__ gl,
                                               const float* __restrict__ gb,
                                               const float* __restrict__ mg) {
    int bg = blockIdx.x * 256 + threadIdx.x;
    if (bg >= BGT) return;
    const float* g = gb + (size_t)bg * 5;
    float gx = g[0], gy = g[1], w = g[2], h = g[3], th = g[4];
    float wc = fmaxf(w, EPSF), hc = fmaxf(h, EPSF);
    float area = wc * hc;
    float ar = fmaxf(wc / hc, hc / wc);
    float sev = fminf(fmaxf((0.01f - area) / (0.01f + EPSF), 0.f), 1.f);
    int te = (int)ceilf(sev * 4.f);
    int el = (ar >= 4.f) ? 1 : 0;
    GTC q;
    q.gx = gx; q.gy = gy;
    q.ct = cosf(-th); q.st = sinf(-th);
    q.w15 = w * 1.5f; q.h15 = h * 1.5f;
    float sc = sqrtf(w * h);
    float is = 1.f / (sc + 1e-6f);
    q.inv_s2 = is * is;
    q.s6 = 6.f * q.inv_s2;
    float isc = 1.f / (sc * 1.5f + 1e-6f);
    q.inv_sc2 = isc * isc;
    float strength = fminf(fmaxf((ar - 4.f) / (4.f + EPSF), 0.f), 1.f);
    float factor = (1.f + sev * (4.f / 13.f)) * (1.f + 0.25f * strength);
    q.gth = th;
    q.budget = 13 + te + el;
    q.fbk = te + el + 3;
    int fl = (mg[bg] > 0.f) ? 1 : 0;
    if ((area < 0.01f) || (ar >= 4.f)) fl |= 2;
    q.flags = fl;
    q.lbl = gl[bg];
    if (!(fl & 1)) factor = 0.f;       // masked GT: lf = -inf -> body yields 0
    q.lf = __logf(factor);
    q.pad = 0;
    d_gt[bg] = q;
    d_cnt[bg] = 0;
}

// ---------------------------------------------------------------------------
// A: block = (512-anchor tile, b), 512 threads, 1 anchor/thread, 32 warps/SM.
// Straight-line single-exp g-loop; label select via smem table (1 LDS).
// ---------------------------------------------------------------------------
__global__ __launch_bounds__(512) void pair_kernel(const float2* __restrict__ anch,
                                                   const float* __restrict__ ps,
                                                   const float* __restrict__ pbx) {
    int b   = blockIdx.y;
    int tid = threadIdx.x;
    int n   = blockIdx.x * 512 + tid;

    __shared__ GTC           s_gt[GG];        // 8 KB
    __shared__ float         s_lcl[NCL][512]; // 10 KB
    __shared__ unsigned char s_any[GG];

    {
        const float4* src = (const float4*)(d_gt + b * GG);
        float4*       dst = (float4*)s_gt;
        dst[tid] = src[tid];
        if (tid < GG) s_any[tid] = 0;
    }

    bool valid = (n < NN);
    float ax = 0.f, ay = 0.f, px = 0.f, py = 0.f, pt = 0.f;
    {
        float l0 = 0.f, l1 = 0.f, l2 = 0.f, l3 = 0.f, l4 = 0.f;
        if (valid) {
            float2 a = anch[n];
            ax = a.x; ay = a.y;
            size_t base = (size_t)(b * NN + n) * 5;
            px = pbx[base]; py = pbx[base + 1]; pt = pbx[base + 4];
#define LC(d, i) { float sg = 1.f/(1.f+__expf(-ps[base+(i)])); \
                   sg = fminf(fmaxf(sg, EPSF), 1.f); d = 0.5f*__logf(sg+EPSF); }
            LC(l0,0) LC(l1,1) LC(l2,2) LC(l3,3) LC(l4,4)
#undef LC
        }
        s_lcl[0][tid] = l0; s_lcl[1][tid] = l1; s_lcl[2][tid] = l2;
        s_lcl[3][tid] = l3; s_lcl[4][tid] = l4;
    }
    __syncthreads();

    float bv = 0.f;
    int   bgi = 0;
    float* amp = d_am + (size_t)b * GG * NN + n;

#pragma unroll 2
    for (int g = 0; g < GG; g++) {
        GTC q = s_gt[g];
        float dxa = ax - q.gx, dya = ay - q.gy;
        float lx = dxa * q.ct - dya * q.st;
        float ly = dxa * q.st + dya * q.ct;
        bool in = valid && (fabsf(lx) < q.w15) && (fabsf(ly) < q.h15);

        float dxp = px - q.gx, dyp = py - q.gy;
        float t6 = (dxp * dxp + dyp * dyp) * q.s6;
        float wv = (pt - q.gth) + HPI_F;
        wv -= PI_F * floorf(wv * IPI_F);
        float wr = fabsf(wv - HPI_F);
        float c = (dxa * dxa + dya * dya) * q.inv_sc2;
        float lcl = s_lcl[q.lbl][tid];
        float val = fmaxf(__expf(q.lf + lcl - t6 - 1.5f * wr - c), 0.f);
        float vv = in ? val : 0.f;

        if (in) s_any[g] = 1;
        if (valid) amp[(size_t)g * NN] = vv;
        if (vv > bv) { bv = vv; bgi = g; }
    }
    __syncthreads();
    if (tid < GG && s_any[tid]) atomicOr(&d_cnt[b * GG + tid], 1);
    if (valid) {
        int idx = b * NN + n;
        d_best[idx] = ((u64)__float_as_uint(bv) << 32) | (unsigned)(127 - bgi);
        d_norm[idx] = 0;
        d_pos[idx]  = 0;
    }
}

// ---------------------------------------------------------------------------
// B (pinned): block per (b,g). Copy row + column maxima in one pass,
// then warp-0-only 18-round extraction. Column c holds i = c + k*256, n=4i+j.
// ---------------------------------------------------------------------------
__global__ __launch_bounds__(256) void topk_kernel(const float2* __restrict__ anch,
                                                   const float* __restrict__ ps,
                                                   const float* __restrict__ pbx) {
    int bg = blockIdx.x;
    int b  = bg >> 7;
    GTC q = d_gt[bg];
    if (!(q.flags & 1)) return;

    int tid = threadIdx.x, lane = tid & 31, wid = tid >> 5;

    __shared__ float    s_av[NN];          // 33.6 KB
    __shared__ u64      s_cmax[256];
    __shared__ u64      s_rm[256];
    __shared__ u64      s_red[8];
    __shared__ unsigned s_chosen[8];

    const float4* am4 = (const float4*)(d_am + (size_t)bg * NN);
    float4*       av4 = (float4*)s_av;
    bool fb = (d_cnt[bg] == 0) && (q.flags & 2);

    u64 cm = 0;
    for (int i = tid; i < NQ4; i += 256) {
        float4 v = am4[i];
        av4[i] = v;
        float m4 = fmaxf(fmaxf(v.x, v.y), fmaxf(v.z, v.w));
        int j = (v.x == m4) ? 0 : ((v.y == m4) ? 1 : ((v.z == m4) ? 2 : 3));
        u64 key = ((u64)__float_as_uint(m4) << 32) | (unsigned)(16384 - (4 * i + j));
        if (key > cm) cm = key;
    }
    s_rm[tid] = 0;

    // -------- tiny/elongated fallback (rare) --------
    if (fb) {
        __syncthreads();
        for (int r = 0; r < 8; r++) {
            u64 key = 0xFFFFFFFFFFFFFFFFull;
            for (int n = tid; n < NN; n += 256) {
                bool skip = false;
                for (int qq = 0; qq < r; qq++)
                    if (s_chosen[qq] == (unsigned)n) skip = true;
                if (!skip) {
                    float2 a = anch[n];
                    float dx = a.x - q.gx, dy = a.y - q.gy;
                    float d2 = dx * dx + dy * dy;
                    u64 k = ((u64)__float_as_uint(d2) << 32) | (unsigned)n;
                    if (k < key) key = k;
                }
            }
#pragma unroll
            for (int o = 16; o; o >>= 1) {
                u64 t = __shfl_xor_sync(0xffffffffu, key, o);
                if (t < key) key = t;
            }
            if (lane == 0) s_red[wid] = key;
            __syncthreads();
            if (wid == 0) {
                u64 v = (lane < 8) ? s_red[lane] : 0xFFFFFFFFFFFFFFFFull;
#pragma unroll
                for (int o = 4; o; o >>= 1) {
                    u64 t = __shfl_xor_sync(0xffffffffu, v, o);
                    if (t < v) v = t;
                }
                if (lane == 0) s_chosen[r] = (unsigned)(v & 0xffffffffu);
            }
            __syncthreads();
            unsigned nw = s_chosen[r];
            if (r < q.fbk && (int)(nw & 255u) == tid) {
                int n = (int)nw;
                float2 a = anch[n];
                float dxa = a.x - q.gx, dya = a.y - q.gy;
                size_t base = (size_t)(b * NN + n) * 5;
                float dxp = pbx[base] - q.gx, dyp = pbx[base + 1] - q.gy;
                float t6 = (dxp * dxp + dyp * dyp) * q.s6;
                float wv = (pbx[base + 4] - q.gth) + HPI_F;
                wv -= PI_F * floorf(wv * IPI_F);
                float wr = fabsf(wv - HPI_F);
                float c = (dxa * dxa + dya * dya) * q.inv_sc2;
                float sg = 1.f / (1.f + __expf(-ps[base + q.lbl]));
                sg = fminf(fmaxf(sg, EPSF), 1.f);
                float lcl = 0.5f * __logf(sg + EPSF);
                float v = fmaxf(__expf(q.lf + lcl - t6 - 1.5f * wr - c), 0.f);
                s_av[n] = v;
                u64 bk = ((u64)__float_as_uint(v) << 32) | (unsigned)(127 - (bg & 127));
                atomicMax((u64*)(d_best + b * NN + n), bk);
            }
            __syncthreads();
        }
        // recompute column maxima after patches
        cm = 0;
        for (int i = tid; i < NQ4; i += 256) {
            float4 v = av4[i];
            float m4 = fmaxf(fmaxf(v.x, v.y), fmaxf(v.z, v.w));
            int j = (v.x == m4) ? 0 : ((v.y == m4) ? 1 : ((v.z == m4) ? 2 : 3));
            u64 key = ((u64)__float_as_uint(m4) << 32) | (unsigned)(16384 - (4 * i + j));
            if (key > cm) cm = key;
        }
    }

    s_cmax[tid] = cm;
    __syncthreads();
    if (wid != 0) return;

    // -------- warp-0-only 18-round extraction --------
    u64 myk[8];
#pragma unroll
    for (int j2 = 0; j2 < 8; j2++) myk[j2] = s_cmax[lane * 8 + j2];
    u64 topkey = 0;

    for (int r = 0; r < MAXTK; r++) {
        u64 m = myk[0];
#pragma unroll
        for (int j2 = 1; j2 < 8; j2++) if (myk[j2] > m) m = myk[j2];
        unsigned hi = (unsigned)(m >> 32);
        unsigned hmax = __reduce_max_sync(0xffffffffu, hi);
        unsigned lo = (hi == hmax) ? (unsigned)m : 0u;
        unsigned lmax = __reduce_max_sync(0xffffffffu, lo);
        if (lane == r) topkey = ((u64)hmax << 32) | lmax;

        int bn = 16384 - (int)lmax;
        int bi = bn >> 2;
        int c  = bi & 255;
        int mi = ((bi >> 8) << 2) | (bn & 3);
        if (lane == 0) s_rm[c] |= (1ull << mi);
        __syncwarp();
        u64 rmm = s_rm[c];
        int nv = (c < (NQ4 & 255)) ? 36 : 32;
        u64 nk = 0;
        {
            int mm = lane;
            if (!((rmm >> mm) & 1ull)) {
                int n2 = 4 * (c + (mm >> 2) * 256) + (mm & 3);
                nk = ((u64)__float_as_uint(s_av[n2]) << 32) | (unsigned)(16384 - n2);
            }
            if (nv == 36 && lane < 4) {
                int mm2 = 32 + lane;
                if (!((rmm >> mm2) & 1ull)) {
                    int n2 = 4 * (c + (mm2 >> 2) * 256) + (mm2 & 3);
                    u64 k2 = ((u64)__float_as_uint(s_av[n2]) << 32) | (unsigned)(16384 - n2);
                    if (k2 > nk) nk = k2;
                }
            }
        }
        unsigned h2 = (unsigned)(nk >> 32);
        unsigned hm2 = __reduce_max_sync(0xffffffffu, h2);
        unsigned lo2 = (h2 == hm2) ? (unsigned)nk : 0u;
        unsigned lm2 = __reduce_max_sync(0xffffffffu, lo2);
        u64 newmax = ((u64)hm2 << 32) | lm2;
        if (lane == (c >> 3)) {
            switch (c & 7) {
                case 0: myk[0] = newmax; break;
                case 1: myk[1] = newmax; break;
                case 2: myk[2] = newmax; break;
                case 3: myk[3] = newmax; break;
                case 4: myk[4] = newmax; break;
                case 5: myk[5] = newmax; break;
                case 6: myk[6] = newmax; break;
                case 7: myk[7] = newmax; break;
            }
        }
    }

    // -------- epilogue (warp 0) --------
    {
        float val = 0.f; unsigned nj = 0; float ovj = 0.f;
        if (lane < MAXTK) {
            val = __uint_as_float((unsigned)(topkey >> 32));
            nj = 16384u - (unsigned)(topkey & 0xffffffffull);
            size_t base = (size_t)(b * NN + nj) * 5;
            float dx = pbx[base] - q.gx, dy = pbx[base + 1] - q.gy;
            float t = (dx * dx + dy * dy) * q.inv_s2;
            ovj = fminf(fmaxf(__expf(-t), 0.f), 1.f);
        }
        float s = ovj;
#pragma unroll
        for (int o = 16; o; o >>= 1) s += __shfl_xor_sync(0xffffffffu, s, o);
        float dk = rintf(s);
        dk = fmaxf(dk, 1.f);
        dk = fminf(dk, (float)q.budget);
        int dyn = (int)dk;
        bool sel = (lane < MAXTK) && (val > EPSF) && (lane < dyn);
        unsigned bal = __ballot_sync(0xffffffffu, sel);
        if (bal) {
            int first = __ffs(bal) - 1;
            float maxalign = __shfl_sync(0xffffffffu, val, first);
            float mo = sel ? ovj : 0.f;
#pragma unroll
            for (int o = 16; o; o >>= 1) mo = fmaxf(mo, __shfl_xor_sync(0xffffffffu, mo, o));
            if (sel) {
                float nv2 = val * mo / (maxalign + EPSF);
                atomicMax(d_norm + b * NN + nj, __float_as_int(nv2));
                d_pos[b * NN + nj] = 1;
            }
        }
    }
}

// ---------------------------------------------------------------------------
__global__ __launch_bounds__(256) void out_kernel(const int* __restrict__ gl,
                                                  const float* __restrict__ gb,
                                                  float* __restrict__ out) {
    int idx = blockIdx.x * 256 + threadIdx.x;
    if (idx >= BN) return;
    int b = idx / NN;
    u64 key = d_best[idx];
    int g = 127 - (int)(key & 0xffffffffull);
    bool pos = d_pos[idx] != 0;
    int lab = gl[b * GG + g];
    out[idx] = pos ? (float)lab : 5.f;
    const float* gp = gb + (size_t)(b * GG + g) * 5;
    float* ob = out + BN + (size_t)idx * 5;
    ob[0] = gp[0]; ob[1] = gp[1]; ob[2] = gp[2]; ob[3] = gp[3]; ob[4] = gp[4];
    float nv = __int_as_float(d_norm[idx]);
    float* os = out + (size_t)BN * 6 + (size_t)idx * 5;
#pragma unroll
    for (int c = 0; c < 5; c++) os[c] = (pos && c == lab) ? nv : 0.f;
    out[(size_t)BN * 11 + idx] = pos ? 1.f : 0.f;
}

// ---------------------------------------------------------------------------
extern "C" void kernel_launch(void* const* d_in, const int* in_sizes, int n_in,
                              void* d_out, int out_size) {
    const float* ps  = (const float*)d_in[0];
    const float* pbx = (const float*)d_in[1];
    const float* ap  = (const float*)d_in[2];
    const int*   gl  = (const int*)d_in[3];
    const float* gbx = (const float*)d_in[4];
    const float* mg  = (const float*)d_in[5];

    prep_gt<<<(BGT + 255) / 256, 256>>>(gl, gbx, mg);
    dim3 ga((NN + 511) / 512, BB);
    pair_kernel<<<ga, 512>>>((const float2*)ap, ps, pbx);
    topk_kernel<<<BGT, 256>>>((const float2*)ap, ps, pbx);
    out_kernel<<<(BN + 255) / 256, 256>>>(gl, gbx, (float*)d_out);
}

// round 17
// speedup vs baseline: 1.2415x; 1.0016x over previous
#include <cuda_runtime.h>
#include <math.h>

#define BB 16
#define NN 8400
#define GG 128
#define NCL 5
#define BN (BB*NN)      // 134400
#define BGT (BB*GG)     // 2048
#define NQ4 (NN/4)      // 2100 float4s per row
#define NTILE 17        // ceil(8400/512)
#define MAXTK 18
#define EPSF 1e-9f
#define HPI_F 1.57079632679489662f
#define PI_F  3.14159265358979323f
#define IPI_F 0.318309886183790672f

typedef unsigned long long u64;

// Field order matters: pair's g-loop touches only the first 3 float4s.
struct GTC {
    float gx, gy, ct, st;          // f4 #0
    float w15, h15, s6, inv_sc2;   // f4 #1   s6 = 6*inv_s2
    float lf, gth; int lbl; float inv_s2;  // f4 #2   lf = log(factor), -inf if masked
    int budget, fbk, flags, pad;   // f4 #3  (topk-only)
};

__device__ float         d_am[(size_t)BGT * NN];  // [b][g][n]
__device__ u64           d_best[BN];              // (val<<32)|(127-g)
__device__ int           d_norm[BN];
__device__ unsigned char d_pos[BN];
__device__ unsigned char d_any[BB * NTILE * GG];  // per-(b,tile,g) in-center flag

// ---------------------------------------------------------------------------
__device__ __forceinline__ GTC make_gtc(int bg, const int* __restrict__ gl,
                                        const float* __restrict__ gb,
                                        const float* __restrict__ mg) {
    const float* g = gb + (size_t)bg * 5;
    float gx = g[0], gy = g[1], w = g[2], h = g[3], th = g[4];
    float wc = fmaxf(w, EPSF), hc = fmaxf(h, EPSF);
    float area = wc * hc;
    float ar = fmaxf(wc / hc, hc / wc);
    float sev = fminf(fmaxf((0.01f - area) / (0.01f + EPSF), 0.f), 1.f);
    int te = (int)ceilf(sev * 4.f);
    int el = (ar >= 4.f) ? 1 : 0;
    GTC q;
    q.gx = gx; q.gy = gy;
    q.ct = cosf(-th); q.st = sinf(-th);
    q.w15 = w * 1.5f; q.h15 = h * 1.5f;
    float sc = sqrtf(w * h);
    float is = 1.f / (sc + 1e-6f);
    q.inv_s2 = is * is;
    q.s6 = 6.f * q.inv_s2;
    float isc = 1.f / (sc * 1.5f + 1e-6f);
    q.inv_sc2 = isc * isc;
    float strength = fminf(fmaxf((ar - 4.f) / (4.f + EPSF), 0.f), 1.f);
    float factor = (1.f + sev * (4.f / 13.f)) * (1.f + 0.25f * strength);
    q.gth = th;
    q.budget = 13 + te + el;
    q.fbk = te + el + 3;
    int fl = (mg[bg] > 0.f) ? 1 : 0;
    if ((area < 0.01f) || (ar >= 4.f)) fl |= 2;
    q.flags = fl;
    q.lbl = gl[bg];
    if (!(fl & 1)) factor = 0.f;       // masked GT: lf = -inf -> body yields 0
    q.lf = __logf(factor);
    q.pad = 0;
    return q;
}

// ---------------------------------------------------------------------------
// A: block = (512-anchor tile, b), 512 threads, 1 anchor/thread, 32 warps/SM.
// GT descriptors built in-block (no prep kernel). Straight-line single-exp
// g-loop; label select via smem table.
// ---------------------------------------------------------------------------
__global__ __launch_bounds__(512) void pair_kernel(const float2* __restrict__ anch,
                                                   const float* __restrict__ ps,
                                                   const float* __restrict__ pbx,
                                                   const int* __restrict__ gl,
                                                   const float* __restrict__ gb,
                                                   const float* __restrict__ mg) {
    int b    = blockIdx.y;
    int tile = blockIdx.x;
    int tid  = threadIdx.x;
    int n    = tile * 512 + tid;

    __shared__ GTC           s_gt[GG];        // 8 KB
    __shared__ float         s_lcl[NCL][512]; // 10 KB
    __shared__ unsigned char s_any[GG];

    if (tid < GG) {
        s_gt[tid] = make_gtc(b * GG + tid, gl, gb, mg);
        s_any[tid] = 0;
    }

    bool valid = (n < NN);
    float ax = 0.f, ay = 0.f, px = 0.f, py = 0.f, pt = 0.f;
    {
        float l0 = 0.f, l1 = 0.f, l2 = 0.f, l3 = 0.f, l4 = 0.f;
        if (valid) {
            float2 a = anch[n];
            ax = a.x; ay = a.y;
            size_t base = (size_t)(b * NN + n) * 5;
            px = pbx[base]; py = pbx[base + 1]; pt = pbx[base + 4];
#define LC(d, i) { float sg = 1.f/(1.f+__expf(-ps[base+(i)])); \
                   sg = fminf(fmaxf(sg, EPSF), 1.f); d = 0.5f*__logf(sg+EPSF); }
            LC(l0,0) LC(l1,1) LC(l2,2) LC(l3,3) LC(l4,4)
#undef LC
        }
        s_lcl[0][tid] = l0; s_lcl[1][tid] = l1; s_lcl[2][tid] = l2;
        s_lcl[3][tid] = l3; s_lcl[4][tid] = l4;
    }
    __syncthreads();

    float bv = 0.f;
    int   bgi = 0;
    float* amp = d_am + (size_t)b * GG * NN + n;

#pragma unroll 2
    for (int g = 0; g < GG; g++) {
        GTC q = s_gt[g];
        float dxa = ax - q.gx, dya = ay - q.gy;
        float lx = dxa * q.ct - dya * q.st;
        float ly = dxa * q.st + dya * q.ct;
        bool in = valid && (fabsf(lx) < q.w15) && (fabsf(ly) < q.h15);

        float dxp = px - q.gx, dyp = py - q.gy;
        float t6 = (dxp * dxp + dyp * dyp) * q.s6;
        float wv = (pt - q.gth) + HPI_F;
        wv -= PI_F * floorf(wv * IPI_F);
        float wr = fabsf(wv - HPI_F);
        float c = (dxa * dxa + dya * dya) * q.inv_sc2;
        float lcl = s_lcl[q.lbl][tid];
        float val = fmaxf(__expf(q.lf + lcl - t6 - 1.5f * wr - c), 0.f);
        float vv = in ? val : 0.f;

        if (in) s_any[g] = 1;
        if (valid) amp[(size_t)g * NN] = vv;
        if (vv > bv) { bv = vv; bgi = g; }
    }
    __syncthreads();
    if (tid < GG) d_any[(b * NTILE + tile) * GG + tid] = s_any[tid];
    if (valid) {
        int idx = b * NN + n;
        d_best[idx] = ((u64)__float_as_uint(bv) << 32) | (unsigned)(127 - bgi);
        d_norm[idx] = 0;
        d_pos[idx]  = 0;
    }
}

// ---------------------------------------------------------------------------
// B (pinned structure): block per (b,g). Own GTC, bitmap-OR fallback check,
// copy row + column maxima in one pass, warp-0-only 18-round extraction.
// Column c holds i = c + k*256, n = 4i+j.
// ---------------------------------------------------------------------------
__global__ __launch_bounds__(256) void topk_kernel(const float2* __restrict__ anch,
                                                   const float* __restrict__ ps,
                                                   const float* __restrict__ pbx,
                                                   const int* __restrict__ gl,
                                                   const float* __restrict__ gb,
                                                   const float* __restrict__ mg) {
    int bg = blockIdx.x;
    int b  = bg >> 7;
    int g  = bg & 127;
    GTC q = make_gtc(bg, gl, gb, mg);
    if (!(q.flags & 1)) return;

    int tid = threadIdx.x, lane = tid & 31, wid = tid >> 5;

    __shared__ float    s_av[NN];          // 33.6 KB
    __shared__ u64      s_cmax[256];
    __shared__ u64      s_rm[256];
    __shared__ u64      s_red[8];
    __shared__ unsigned s_chosen[8];

    const float4* am4 = (const float4*)(d_am + (size_t)bg * NN);
    float4*       av4 = (float4*)s_av;

    bool fb = (q.flags & 2) != 0;
    if (fb) {
        int any = 0;
#pragma unroll
        for (int t = 0; t < NTILE; t++) any |= d_any[(b * NTILE + t) * GG + g];
        fb = (any == 0);
    }

    u64 cm = 0;
    for (int i = tid; i < NQ4; i += 256) {
        float4 v = am4[i];
        av4[i] = v;
        float m4 = fmaxf(fmaxf(v.x, v.y), fmaxf(v.z, v.w));
        int j = (v.x == m4) ? 0 : ((v.y == m4) ? 1 : ((v.z == m4) ? 2 : 3));
        u64 key = ((u64)__float_as_uint(m4) << 32) | (unsigned)(16384 - (4 * i + j));
        if (key > cm) cm = key;
    }
    s_rm[tid] = 0;

    // -------- tiny/elongated fallback (rare) --------
    if (fb) {
        __syncthreads();
        for (int r = 0; r < 8; r++) {
            u64 key = 0xFFFFFFFFFFFFFFFFull;
            for (int n = tid; n < NN; n += 256) {
                bool skip = false;
                for (int qq = 0; qq < r; qq++)
                    if (s_chosen[qq] == (unsigned)n) skip = true;
                if (!skip) {
                    float2 a = anch[n];
                    float dx = a.x - q.gx, dy = a.y - q.gy;
                    float d2 = dx * dx + dy * dy;
                    u64 k = ((u64)__float_as_uint(d2) << 32) | (unsigned)n;
                    if (k < key) key = k;
                }
            }
#pragma unroll
            for (int o = 16; o; o >>= 1) {
                u64 t = __shfl_xor_sync(0xffffffffu, key, o);
                if (t < key) key = t;
            }
            if (lane == 0) s_red[wid] = key;
            __syncthreads();
            if (wid == 0) {
                u64 v = (lane < 8) ? s_red[lane] : 0xFFFFFFFFFFFFFFFFull;
#pragma unroll
                for (int o = 4; o; o >>= 1) {
                    u64 t = __shfl_xor_sync(0xffffffffu, v, o);
                    if (t < v) v = t;
                }
                if (lane == 0) s_chosen[r] = (unsigned)(v & 0xffffffffu);
            }
            __syncthreads();
            unsigned nw = s_chosen[r];
            if (r < q.fbk && (int)(nw & 255u) == tid) {
                int n = (int)nw;
                float2 a = anch[n];
                float dxa = a.x - q.gx, dya = a.y - q.gy;
                size_t base = (size_t)(b * NN + n) * 5;
                float dxp = pbx[base] - q.gx, dyp = pbx[base + 1] - q.gy;
                float t6 = (dxp * dxp + dyp * dyp) * q.s6;
                float wv = (pbx[base + 4] - q.gth) + HPI_F;
                wv -= PI_F * floorf(wv * IPI_F);
                float wr = fabsf(wv - HPI_F);
                float c = (dxa * dxa + dya * dya) * q.inv_sc2;
                float sg = 1.f / (1.f + __expf(-ps[base + q.lbl]));
                sg = fminf(fmaxf(sg, EPSF), 1.f);
                float lcl = 0.5f * __logf(sg + EPSF);
                float v = fmaxf(__expf(q.lf + lcl - t6 - 1.5f * wr - c), 0.f);
                s_av[n] = v;
                u64 bk = ((u64)__float_as_uint(v) << 32) | (unsigned)(127 - g);
                atomicMax((u64*)(d_best + b * NN + n), bk);
            }
            __syncthreads();
        }
        // recompute column maxima after patches
        cm = 0;
        for (int i = tid; i < NQ4; i += 256) {
            float4 v = av4[i];
            float m4 = fmaxf(fmaxf(v.x, v.y), fmaxf(v.z, v.w));
            int j = (v.x == m4) ? 0 : ((v.y == m4) ? 1 : ((v.z == m4) ? 2 : 3));
            u64 key = ((u64)__float_as_uint(m4) << 32) | (unsigned)(16384 - (4 * i + j));
            if (key > cm) cm = key;
        }
    }

    s_cmax[tid] = cm;
    __syncthreads();
    if (wid != 0) return;

    // -------- warp-0-only 18-round extraction --------
    u64 myk[8];
#pragma unroll
    for (int j2 = 0; j2 < 8; j2++) myk[j2] = s_cmax[lane * 8 + j2];
    u64 topkey = 0;

    for (int r = 0; r < MAXTK; r++) {
        u64 m = myk[0];
#pragma unroll
        for (int j2 = 1; j2 < 8; j2++) if (myk[j2] > m) m = myk[j2];
        unsigned hi = (unsigned)(m >> 32);
        unsigned hmax = __reduce_max_sync(0xffffffffu, hi);
        unsigned lo = (hi == hmax) ? (unsigned)m : 0u;
        unsigned lmax = __reduce_max_sync(0xffffffffu, lo);
        if (lane == r) topkey = ((u64)hmax << 32) | lmax;

        int bn = 16384 - (int)lmax;
        int bi = bn >> 2;
        int c  = bi & 255;
        int mi = ((bi >> 8) << 2) | (bn & 3);
        if (lane == 0) s_rm[c] |= (1ull << mi);
        __syncwarp();
        u64 rmm = s_rm[c];
        int nv = (c < (NQ4 & 255)) ? 36 : 32;
        u64 nk = 0;
        {
            int mm = lane;
            if (!((rmm >> mm) & 1ull)) {
                int n2 = 4 * (c + (mm >> 2) * 256) + (mm & 3);
                nk = ((u64)__float_as_uint(s_av[n2]) << 32) | (unsigned)(16384 - n2);
            }
            if (nv == 36 && lane < 4) {
                int mm2 = 32 + lane;
                if (!((rmm >> mm2) & 1ull)) {
                    int n2 = 4 * (c + (mm2 >> 2) * 256) + (mm2 & 3);
                    u64 k2 = ((u64)__float_as_uint(s_av[n2]) << 32) | (unsigned)(16384 - n2);
                    if (k2 > nk) nk = k2;
                }
            }
        }
        unsigned h2 = (unsigned)(nk >> 32);
        unsigned hm2 = __reduce_max_sync(0xffffffffu, h2);
        unsigned lo2 = (h2 == hm2) ? (unsigned)nk : 0u;
        unsigned lm2 = __reduce_max_sync(0xffffffffu, lo2);
        u64 newmax = ((u64)hm2 << 32) | lm2;
        if (lane == (c >> 3)) {
            switch (c & 7) {
                case 0: myk[0] = newmax; break;
                case 1: myk[1] = newmax; break;
                case 2: myk[2] = newmax; break;
                case 3: myk[3] = newmax; break;
                case 4: myk[4] = newmax; break;
                case 5: myk[5] = newmax; break;
                case 6: myk[6] = newmax; break;
                case 7: myk[7] = newmax; break;
            }
        }
    }

    // -------- epilogue (warp 0) --------
    {
        float val = 0.f; unsigned nj = 0; float ovj = 0.f;
        if (lane < MAXTK) {
            val = __uint_as_float((unsigned)(topkey >> 32));
            nj = 16384u - (unsigned)(topkey & 0xffffffffull);
            size_t base = (size_t)(b * NN + nj) * 5;
            float dx = pbx[base] - q.gx, dy = pbx[base + 1] - q.gy;
            float t = (dx * dx + dy * dy) * q.inv_s2;
            ovj = fminf(fmaxf(__expf(-t), 0.f), 1.f);
        }
        float s = ovj;
#pragma unroll
        for (int o = 16; o; o >>= 1) s += __shfl_xor_sync(0xffffffffu, s, o);
        float dk = rintf(s);
        dk = fmaxf(dk, 1.f);
        dk = fminf(dk, (float)q.budget);
        int dyn = (int)dk;
        bool sel = (lane < MAXTK) && (val > EPSF) && (lane < dyn);
        unsigned bal = __ballot_sync(0xffffffffu, sel);
        if (bal) {
            int first = __ffs(bal) - 1;
            float maxalign = __shfl_sync(0xffffffffu, val, first);
            float mo = sel ? ovj : 0.f;
#pragma unroll
            for (int o = 16; o; o >>= 1) mo = fmaxf(mo, __shfl_xor_sync(0xffffffffu, mo, o));
            if (sel) {
                float nv2 = val * mo / (maxalign + EPSF);
                atomicMax(d_norm + b * NN + nj, __float_as_int(nv2));
                d_pos[b * NN + nj] = 1;
            }
        }
    }
}

// ---------------------------------------------------------------------------
// D: smem-staged coalesced bbox/scores stores. BN = 525*256 exactly.
// ---------------------------------------------------------------------------
__global__ __launch_bounds__(256) void out_kernel(const int* __restrict__ gl,
                                                  const float* __restrict__ gb,
                                                  float* __restrict__ out) {
    __shared__ float s_b[1280];
    __shared__ float s_s[1280];
    int tid = threadIdx.x;
    int idx0 = blockIdx.x * 256;
    int idx = idx0 + tid;
    int b = idx / NN;
    u64 key = d_best[idx];
    int g = 127 - (int)(key & 0xffffffffull);
    bool pos = d_pos[idx] != 0;
    int lab = gl[b * GG + g];
    out[idx] = pos ? (float)lab : 5.f;
    out[(size_t)BN * 11 + idx] = pos ? 1.f : 0.f;
    const float* gp = gb + (size_t)(b * GG + g) * 5;
    float nv = __int_as_float(d_norm[idx]);
#pragma unroll
    for (int c = 0; c < 5; c++) {
        s_b[tid * 5 + c] = gp[c];
        s_s[tid * 5 + c] = (pos && c == lab) ? nv : 0.f;
    }
    __syncthreads();
    float4* ob4 = (float4*)(out + BN + (size_t)idx0 * 5);
    float4* os4 = (float4*)(out + (size_t)BN * 6 + (size_t)idx0 * 5);
    const float4* sb4 = (const float4*)s_b;
    const float4* ss4 = (const float4*)s_s;
    ob4[tid] = sb4[tid];
    os4[tid] = ss4[tid];
    if (tid < 64) {
        ob4[256 + tid] = sb4[256 + tid];
        os4[256 + tid] = ss4[256 + tid];
    }
}

// ---------------------------------------------------------------------------
extern "C" void kernel_launch(void* const* d_in, const int* in_sizes, int n_in,
                              void* d_out, int out_size) {
    const float* ps  = (const float*)d_in[0];
    const float* pbx = (const float*)d_in[1];
    const float* ap  = (const float*)d_in[2];
    const int*   gl  = (const int*)d_in[3];
    const float* gbx = (const float*)d_in[4];
    const float* mg  = (const float*)d_in[5];

    dim3 ga(NTILE, BB);
    pair_kernel<<<ga, 512>>>((const float2*)ap, ps, pbx, gl, gbx, mg);
    topk_kernel<<<BGT, 256>>>((const float2*)ap, ps, pbx, gl, gbx, mg);
    out_kernel<<<BN / 256, 256>>>(gl, gbx, (float*)d_out);
}